// round 15
// baseline (speedup 1.0000x reference)
#include <cuda_runtime.h>
#include <cuda.h>
#include <cstdint>
#include <cstddef>

// Problem constants
#define BB 8
#define CCT 128
#define HH 128
#define WW 128
#define RR 4
#define NOFF 81

// Tiling: 8x32 pixel tile, 8 px/thread, 32 threads per dy-group, 9 groups
// 288 threads/CTA, 2 CTAs per SM
#define TH 8
#define TW 32
#define NGROUP 9
#define NT (NGROUP * 32)      // 288 threads, 9 warps
#define CCH 8                 // channels per chunk
#define NCHUNK (CCT / CCH)    // 16
#define NB 3                  // ring buffers; prefetch distance 2

// Shared layout (floats) — padding achieved via TMA box width (dense box rows)
#define FSTR 36               // first box width: 144B rows -> conflict-free for P=8
#define SSTR 44               // second box width: 176B rows -> conflict-free for P=8
#define SROWS (TH + 2*RR)                 // 16
#define F_CH (TH * FSTR)                  // 288
#define S_CH (SROWS * SSTR)               // 704
#define F_BUF (CCH * F_CH)                // 2304 fl
#define S_BUF (CCH * S_CH)                // 5632 fl
#define F_OFF 0
#define S_OFF (NB * F_BUF)                // 6912 fl
#define SMEM_FLOATS (S_OFF + NB * S_BUF)  // 23808 fl
#define SMEM_BYTES (SMEM_FLOATS * 4)      // 95232 B (x2 CTAs = 190KB/SM)
#define TX_BYTES ((F_BUF + S_BUF) * 4)    // 31744 B per chunk

typedef unsigned long long u64;

__device__ __forceinline__ u64 pk2(float lo, float hi) {
    u64 r;
    asm("mov.b64 %0, {%1, %2};" : "=l"(r) : "f"(lo), "f"(hi));
    return r;
}
__device__ __forceinline__ float lo_f(u64 v) { return __uint_as_float((unsigned)v); }
__device__ __forceinline__ float hi_f(u64 v) { return __uint_as_float((unsigned)(v >> 32)); }

__device__ __forceinline__ void fma2(u64& d, u64 a, u64 b) {
    asm("fma.rn.f32x2 %0, %1, %2, %0;" : "+l"(d) : "l"(a), "l"(b));
}
__device__ __forceinline__ void mbar_init(unsigned a, unsigned cnt) {
    asm volatile("mbarrier.init.shared.b64 [%0], %1;" :: "r"(a), "r"(cnt) : "memory");
}
__device__ __forceinline__ void mbar_arrive(unsigned a) {
    asm volatile("mbarrier.arrive.shared.b64 _, [%0];" :: "r"(a) : "memory");
}
__device__ __forceinline__ void mbar_arrive_tx(unsigned a, unsigned bytes) {
    asm volatile("mbarrier.arrive.expect_tx.shared.b64 _, [%0], %1;"
                 :: "r"(a), "r"(bytes) : "memory");
}
__device__ __forceinline__ void mbar_wait(unsigned a, unsigned ph) {
    asm volatile(
        "{\n\t.reg .pred p;\n"
        "W_%=:\n\t"
        "mbarrier.try_wait.parity.acquire.cta.shared::cta.b64 p, [%0], %1, 0x989680;\n\t"
        "@!p bra W_%=;\n\t}"
        :: "r"(a), "r"(ph) : "memory");
}
__device__ __forceinline__ void tma4d(unsigned dst, const CUtensorMap* tm,
                                      int x, int y, int z, int w, unsigned mbar) {
    asm volatile(
        "cp.async.bulk.tensor.4d.shared::cta.global.tile.mbarrier::complete_tx::bytes "
        "[%0], [%1, {%2, %3, %4, %5}], [%6];"
        :: "r"(dst), "l"(tm), "r"(x), "r"(y), "r"(z), "r"(w), "r"(mbar)
        : "memory");
}

__global__ void __launch_bounds__(NT, 2)
costvol_kernel(const __grid_constant__ CUtensorMap tmF,
               const __grid_constant__ CUtensorMap tmS,
               float* __restrict__ out) {
    extern __shared__ __align__(128) float smem[];
    __shared__ __align__(8) u64 mbar[2 * NB];   // [0..NB) full, [NB..2NB) empty

    const int tid = threadIdx.x;
    const int g   = tid >> 5;            // dy index 0..8
    const int lid = tid & 31;
    const int lh  = lid >> 2;            // local row 0..7
    const int lw  = (lid & 3) << 3;      // local col base {0,8,16,24}
    const int lane = tid & 31;

    const int w0 = blockIdx.x * TW;
    const int h0 = blockIdx.y * TH;
    const int bz = blockIdx.z;

    const unsigned smem_u = (unsigned)__cvta_generic_to_shared(smem);
    const unsigned mb0    = (unsigned)__cvta_generic_to_shared(mbar);

    // ---------- mbarrier init ----------
    if (tid == 0) {
#pragma unroll
        for (int b = 0; b < NB; b++) {
            mbar_init(mb0 + b * 8, 1);               // full[b]: producer arrive
            mbar_init(mb0 + (NB + b) * 8, NGROUP);   // empty[b]: 9 warp arrives
        }
    }
    __syncthreads();

    // ---------- producer: one TMA pair per chunk ----------
    auto issue = [&](int c, int b) {
        const unsigned fullb = mb0 + b * 8;
        mbar_arrive_tx(fullb, TX_BYTES);
        tma4d(smem_u + (S_OFF + b * S_BUF) * 4, &tmS,
              w0 - RR, h0 - RR, c * CCH, bz, fullb);
        tma4d(smem_u + (F_OFF + b * F_BUF) * 4, &tmF,
              w0, h0, c * CCH, bz, fullb);
    };

    if (tid == 0) { issue(0, 0); issue(1, 1); }

    // ---------- accumulators (8 px) ----------
    u64 accE[5][4];           // even dx = 2e; pixel pairs (0,1)(2,3)(4,5)(6,7)
    u64 accO[4][3];           // odd dx = 2o+1; pixel pairs (1,2)(3,4)(5,6)
    float acc0[4], acc7[4];   // odd-dx boundary pixels 0 and 7
#pragma unroll
    for (int e = 0; e < 5; e++)
#pragma unroll
        for (int p = 0; p < 4; p++) accE[e][p] = 0ULL;
#pragma unroll
    for (int o = 0; o < 4; o++) {
#pragma unroll
        for (int p = 0; p < 3; p++) accO[o][p] = 0ULL;
        acc0[o] = 0.f; acc7[o] = 0.f;
    }

    const float* Fbase = smem + F_OFF + lh * FSTR + lw;
    const float* Sbase = smem + S_OFF + (lh + g) * SSTR + lw;

    // pipeline cursors (stage, phase)
    int cstage = 0, cph = 0;          // consumer
    int pstage = 2, pph = 0;          // producer (chunks 0,1 already issued)

#pragma unroll 1
    for (int cc = 0; cc < NCHUNK; cc++) {
        // producer duty: prefetch chunk cc+2 into buffer pstage
        const int c = cc + 2;
        if (c < NCHUNK) {
            if (tid == 0) {
                if (c >= NB)
                    mbar_wait(mb0 + (NB + pstage) * 8, (unsigned)(pph ^ 1));
                issue(c, pstage);
            }
            if (++pstage == NB) { pstage = 0; pph ^= 1; }
        }

        // consume: wait until this chunk's TMA completed
        mbar_wait(mb0 + cstage * 8, (unsigned)cph);

        const float* Fp = Fbase + cstage * F_BUF;
        const float* Sp = Sbase + cstage * S_BUF;

#pragma unroll
        for (int ch = 0; ch < CCH; ch++) {
            const float* fptr = Fp + ch * F_CH;
            const float* sptr = Sp + ch * S_CH;

            // first: 4 aligned pairs + scalar views; 3 odd-packs
            ulonglong2 fA = *(const ulonglong2*)fptr;
            ulonglong2 fB = *(const ulonglong2*)(fptr + 4);
            u64 fp0 = fA.x, fp1 = fA.y, fp2 = fB.x, fp3 = fB.y;
            float f0 = lo_f(fp0), f1 = hi_f(fp0);
            float f2 = lo_f(fp1), f3 = hi_f(fp1);
            float f4 = lo_f(fp2), f5 = hi_f(fp2);
            float f6 = lo_f(fp3), f7 = hi_f(fp3);
            u64 op0 = pk2(f1, f2);
            u64 op1 = pk2(f3, f4);
            u64 op2 = pk2(f5, f6);

            // second window: 16 floats = 8 aligned pairs
            ulonglong2 wA = *(const ulonglong2*)sptr;
            ulonglong2 wB = *(const ulonglong2*)(sptr + 4);
            ulonglong2 wC = *(const ulonglong2*)(sptr + 8);
            ulonglong2 wD = *(const ulonglong2*)(sptr + 12);
            u64 wp[8] = { wA.x, wA.y, wB.x, wB.y, wC.x, wC.y, wD.x, wD.y };

            // even dx = 2e: all operands aligned, zero packs
#pragma unroll
            for (int e = 0; e < 5; e++) {
                fma2(accE[e][0], fp0, wp[0 + e]);
                fma2(accE[e][1], fp1, wp[1 + e]);
                fma2(accE[e][2], fp2, wp[2 + e]);
                fma2(accE[e][3], fp3, wp[3 + e]);
            }
            // odd dx = 2o+1: window pairs aligned; 3 first-packs reused
#pragma unroll
            for (int o = 0; o < 4; o++) {
                fma2(accO[o][0], op0, wp[o + 1]);
                fma2(accO[o][1], op1, wp[o + 2]);
                fma2(accO[o][2], op2, wp[o + 3]);
                acc0[o] = fmaf(f0, hi_f(wp[o]),     acc0[o]);   // w[2o+1]
                acc7[o] = fmaf(f7, lo_f(wp[o + 4]), acc7[o]);   // w[8+2o]
            }
        }

        // release buffer (warp-granular)
        __syncwarp();
        if (lane == 0) mbar_arrive(mb0 + (NB + cstage) * 8);
        if (++cstage == NB) { cstage = 0; cph ^= 1; }
    }

    // ---------- store: mean over C ----------
    const float inv = 1.0f / (float)CCT;
    const size_t row_base = ((size_t)bz * NOFF) * HH * WW
                          + (size_t)(h0 + lh) * WW + (w0 + lw);
#pragma unroll
    for (int e = 0; e < 5; e++) {
        int o = g * 9 + 2 * e;
        float* op = out + row_base + (size_t)o * HH * WW;
        float4 v0 = make_float4(lo_f(accE[e][0]) * inv, hi_f(accE[e][0]) * inv,
                                lo_f(accE[e][1]) * inv, hi_f(accE[e][1]) * inv);
        float4 v1 = make_float4(lo_f(accE[e][2]) * inv, hi_f(accE[e][2]) * inv,
                                lo_f(accE[e][3]) * inv, hi_f(accE[e][3]) * inv);
        *(float4*)op       = v0;
        *(float4*)(op + 4) = v1;
    }
#pragma unroll
    for (int o2 = 0; o2 < 4; o2++) {
        int o = g * 9 + 2 * o2 + 1;
        float* op = out + row_base + (size_t)o * HH * WW;
        float4 v0 = make_float4(acc0[o2] * inv,
                                lo_f(accO[o2][0]) * inv, hi_f(accO[o2][0]) * inv,
                                lo_f(accO[o2][1]) * inv);
        float4 v1 = make_float4(hi_f(accO[o2][1]) * inv,
                                lo_f(accO[o2][2]) * inv, hi_f(accO[o2][2]) * inv,
                                acc7[o2] * inv);
        *(float4*)op       = v0;
        *(float4*)(op + 4) = v1;
    }
}

typedef CUresult (*TmapEncodeFn)(
    CUtensorMap*, CUtensorMapDataType, cuuint32_t, void*,
    const cuuint64_t*, const cuuint64_t*, const cuuint32_t*, const cuuint32_t*,
    CUtensorMapInterleave, CUtensorMapSwizzle, CUtensorMapL2promotion,
    CUtensorMapFloatOOBfill);

extern "C" void kernel_launch(void* const* d_in, const int* in_sizes, int n_in,
                              void* d_out, int out_size) {
    (void)in_sizes; (void)n_in; (void)out_size;
    void* first_p  = d_in[0];
    void* second_p = d_in[1];
    float* out = (float*)d_out;

    // Fetch cuTensorMapEncodeTiled via cudart (no -lcuda link dependency)
    void* sym = nullptr;
    cudaDriverEntryPointQueryResult qr;
    cudaGetDriverEntryPointByVersion("cuTensorMapEncodeTiled", &sym, 12000,
                                     cudaEnableDefault, &qr);
    TmapEncodeFn enc = (TmapEncodeFn)sym;

    cuuint64_t dims[4]    = { WW, HH, CCT, BB };
    cuuint64_t strides[3] = { (cuuint64_t)WW * 4,
                              (cuuint64_t)HH * WW * 4,
                              (cuuint64_t)CCT * HH * WW * 4 };
    cuuint32_t es[4]   = { 1, 1, 1, 1 };
    cuuint32_t boxS[4] = { SSTR, SROWS, CCH, 1 };   // 44 x 16 x 8 x 1 (176B rows)
    cuuint32_t boxF[4] = { FSTR, TH, CCH, 1 };      // 36 x 8 x 8 x 1 (144B rows)

    CUtensorMap tmS, tmF;
    enc(&tmS, CU_TENSOR_MAP_DATA_TYPE_FLOAT32, 4, second_p,
        dims, strides, boxS, es,
        CU_TENSOR_MAP_INTERLEAVE_NONE, CU_TENSOR_MAP_SWIZZLE_NONE,
        CU_TENSOR_MAP_L2_PROMOTION_L2_256B, CU_TENSOR_MAP_FLOAT_OOB_FILL_NONE);
    enc(&tmF, CU_TENSOR_MAP_DATA_TYPE_FLOAT32, 4, first_p,
        dims, strides, boxF, es,
        CU_TENSOR_MAP_INTERLEAVE_NONE, CU_TENSOR_MAP_SWIZZLE_NONE,
        CU_TENSOR_MAP_L2_PROMOTION_L2_256B, CU_TENSOR_MAP_FLOAT_OOB_FILL_NONE);

    cudaFuncSetAttribute(costvol_kernel,
                         cudaFuncAttributeMaxDynamicSharedMemorySize, SMEM_BYTES);

    dim3 grid(WW / TW, HH / TH, BB);   // (4,16,8) = 512 blocks
    costvol_kernel<<<grid, NT, SMEM_BYTES>>>(tmF, tmS, out);
}

// round 16
// speedup vs baseline: 1.3891x; 1.3891x over previous
#include <cuda_runtime.h>
#include <cuda.h>
#include <cstdint>
#include <cstddef>

// Problem constants
#define BB 8
#define CCT 128
#define HH 128
#define WW 128
#define RR 4
#define NOFF 81

// Tiling: 4x32 pixel tile, 4 px/thread, 32 threads per dy-group, 9 groups
// 288 threads/CTA, 3 CTAs per SM (reg cap 75 -> packed accumulators)
#define TH 4
#define TW 32
#define NGROUP 9
#define NT (NGROUP * 32)      // 288 threads, 9 warps
#define CCH 8                 // channels per chunk
#define NCHUNK (CCT / CCH)    // 16
#define NB 3                  // ring buffers; prefetch distance 2

// Shared layout (floats) — TMA box-dense strides
#define FSTR 32               // first row stride (= box width)
#define SSTR 40               // second row stride (= box width)
#define SROWS 12
#define F_CH (TH * FSTR)                  // 128
#define S_CH (SROWS * SSTR)               // 480
#define F_BUF (CCH * F_CH)                // 1024 fl = 4096 B
#define S_BUF (CCH * S_CH)                // 3840 fl = 15360 B
#define F_OFF 0
#define S_OFF (NB * F_BUF)                // 3072 fl
#define SMEM_FLOATS (S_OFF + NB * S_BUF)  // 14592 fl
#define SMEM_BYTES (SMEM_FLOATS * 4)      // 58368 B (x3 CTAs = 175KB/SM)
#define TX_BYTES ((F_BUF + S_BUF) * 4)    // 19456 B per chunk

typedef unsigned long long u64;

__device__ __forceinline__ u64 pk2(float lo, float hi) {
    u64 r;
    asm("mov.b64 %0, {%1, %2};" : "=l"(r) : "f"(lo), "f"(hi));
    return r;
}
__device__ __forceinline__ float lo_f(u64 v) { return __uint_as_float((unsigned)v); }
__device__ __forceinline__ float hi_f(u64 v) { return __uint_as_float((unsigned)(v >> 32)); }

__device__ __forceinline__ void fma2(u64& d, u64 a, u64 b) {
    asm("fma.rn.f32x2 %0, %1, %2, %0;" : "+l"(d) : "l"(a), "l"(b));
}
__device__ __forceinline__ void mbar_init(unsigned a, unsigned cnt) {
    asm volatile("mbarrier.init.shared.b64 [%0], %1;" :: "r"(a), "r"(cnt) : "memory");
}
__device__ __forceinline__ void mbar_arrive(unsigned a) {
    asm volatile("mbarrier.arrive.shared.b64 _, [%0];" :: "r"(a) : "memory");
}
__device__ __forceinline__ void mbar_arrive_tx(unsigned a, unsigned bytes) {
    asm volatile("mbarrier.arrive.expect_tx.shared.b64 _, [%0], %1;"
                 :: "r"(a), "r"(bytes) : "memory");
}
__device__ __forceinline__ void mbar_wait(unsigned a, unsigned ph) {
    asm volatile(
        "{\n\t.reg .pred p;\n"
        "W_%=:\n\t"
        "mbarrier.try_wait.parity.acquire.cta.shared::cta.b64 p, [%0], %1, 0x989680;\n\t"
        "@!p bra W_%=;\n\t}"
        :: "r"(a), "r"(ph) : "memory");
}
__device__ __forceinline__ void tma4d(unsigned dst, const CUtensorMap* tm,
                                      int x, int y, int z, int w, unsigned mbar) {
    asm volatile(
        "cp.async.bulk.tensor.4d.shared::cta.global.tile.mbarrier::complete_tx::bytes "
        "[%0], [%1, {%2, %3, %4, %5}], [%6];"
        :: "r"(dst), "l"(tm), "r"(x), "r"(y), "r"(z), "r"(w), "r"(mbar)
        : "memory");
}

__global__ void __launch_bounds__(NT, 3)
costvol_kernel(const __grid_constant__ CUtensorMap tmF,
               const __grid_constant__ CUtensorMap tmS,
               float* __restrict__ out) {
    extern __shared__ __align__(128) float smem[];
    __shared__ __align__(8) u64 mbar[2 * NB];   // [0..NB) full, [NB..2NB) empty

    const int tid = threadIdx.x;
    const int g   = tid >> 5;            // dy index 0..8
    const int lid = tid & 31;
    const int lh  = lid >> 3;            // local row 0..3
    const int lw  = (lid & 7) << 2;      // local col base {0,4,...,28}
    const int lane = tid & 31;

    const int w0 = blockIdx.x * TW;
    const int h0 = blockIdx.y * TH;
    const int bz = blockIdx.z;

    const unsigned smem_u = (unsigned)__cvta_generic_to_shared(smem);
    const unsigned mb0    = (unsigned)__cvta_generic_to_shared(mbar);

    // ---------- mbarrier init ----------
    if (tid == 0) {
#pragma unroll
        for (int b = 0; b < NB; b++) {
            mbar_init(mb0 + b * 8, 1);               // full[b]: producer arrive
            mbar_init(mb0 + (NB + b) * 8, NGROUP);   // empty[b]: 9 warp arrives
        }
    }
    __syncthreads();

    // ---------- producer: one TMA pair per chunk ----------
    auto issue = [&](int c, int b) {
        const unsigned fullb = mb0 + b * 8;
        mbar_arrive_tx(fullb, TX_BYTES);
        tma4d(smem_u + (S_OFF + b * S_BUF) * 4, &tmS,
              w0 - RR, h0 - RR, c * CCH, bz, fullb);
        tma4d(smem_u + (F_OFF + b * F_BUF) * 4, &tmF,
              w0, h0, c * CCH, bz, fullb);
    };

    if (tid == 0) { issue(0, 0); issue(1, 1); }

    // ---------- accumulators (4 px, fully packed) ----------
    u64 accE[5][2];           // even dx = 2e; pixel pairs (0,1)(2,3)
    u64 accO[4];              // odd dx = 2o+1; pixel pair (1,2)
    u64 accB[4];              // odd dx boundary: (pixel0, pixel3) packed
#pragma unroll
    for (int e = 0; e < 5; e++) { accE[e][0] = 0ULL; accE[e][1] = 0ULL; }
#pragma unroll
    for (int o = 0; o < 4; o++) { accO[o] = 0ULL; accB[o] = 0ULL; }

    const float* Fbase = smem + F_OFF + lh * FSTR + lw;
    const float* Sbase = smem + S_OFF + (lh + g) * SSTR + lw;

    // pipeline cursors (stage, phase)
    int cstage = 0, cph = 0;          // consumer
    int pstage = 2, pph = 0;          // producer (chunks 0,1 already issued)

#pragma unroll 1
    for (int cc = 0; cc < NCHUNK; cc++) {
        // producer duty: prefetch chunk cc+2 into buffer pstage
        const int c = cc + 2;
        if (c < NCHUNK) {
            if (tid == 0) {
                if (c >= NB)
                    mbar_wait(mb0 + (NB + pstage) * 8, (unsigned)(pph ^ 1));
                issue(c, pstage);
            }
            if (++pstage == NB) { pstage = 0; pph ^= 1; }
        }

        // consume: wait until this chunk's TMA completed
        mbar_wait(mb0 + cstage * 8, (unsigned)cph);

        const float* Fp = Fbase + cstage * F_BUF;
        const float* Sp = Sbase + cstage * S_BUF;

#pragma unroll
        for (int ch = 0; ch < CCH; ch++) {
            const float* fptr = Fp + ch * F_CH;
            const float* sptr = Sp + ch * S_CH;

            // first: 2 aligned pairs; odd-pack + boundary-pack
            ulonglong2 fA = *(const ulonglong2*)fptr;
            u64 fp0 = fA.x, fp1 = fA.y;
            float f0 = lo_f(fp0), f1 = hi_f(fp0);
            float f2 = lo_f(fp1), f3 = hi_f(fp1);
            u64 op0 = pk2(f1, f2);
            u64 fb  = pk2(f0, f3);

            // second window: 12 floats = 6 aligned pairs
            ulonglong2 wA = *(const ulonglong2*)sptr;
            ulonglong2 wB = *(const ulonglong2*)(sptr + 4);
            ulonglong2 wC = *(const ulonglong2*)(sptr + 8);
            u64 wp[6] = { wA.x, wA.y, wB.x, wB.y, wC.x, wC.y };

            // even dx = 2e: aligned, zero packs
#pragma unroll
            for (int e = 0; e < 5; e++) {
                fma2(accE[e][0], fp0, wp[e]);
                fma2(accE[e][1], fp1, wp[e + 1]);
            }
            // odd dx = 2o+1: middle pair aligned; boundaries packed (px0,px3)
#pragma unroll
            for (int o = 0; o < 4; o++) {
                fma2(accO[o], op0, wp[o + 1]);
                u64 wb = pk2(hi_f(wp[o]), lo_f(wp[o + 2]));  // (w[2o+1], w[2o+4])
                fma2(accB[o], fb, wb);
            }
        }

        // release buffer (warp-granular)
        __syncwarp();
        if (lane == 0) mbar_arrive(mb0 + (NB + cstage) * 8);
        if (++cstage == NB) { cstage = 0; cph ^= 1; }
    }

    // ---------- store: mean over C ----------
    const float inv = 1.0f / (float)CCT;
    const size_t row_base = ((size_t)bz * NOFF) * HH * WW
                          + (size_t)(h0 + lh) * WW + (w0 + lw);
#pragma unroll
    for (int e = 0; e < 5; e++) {
        int o = g * 9 + 2 * e;
        float* op = out + row_base + (size_t)o * HH * WW;
        *(float4*)op = make_float4(lo_f(accE[e][0]) * inv, hi_f(accE[e][0]) * inv,
                                   lo_f(accE[e][1]) * inv, hi_f(accE[e][1]) * inv);
    }
#pragma unroll
    for (int o2 = 0; o2 < 4; o2++) {
        int o = g * 9 + 2 * o2 + 1;
        float* op = out + row_base + (size_t)o * HH * WW;
        *(float4*)op = make_float4(lo_f(accB[o2]) * inv,
                                   lo_f(accO[o2]) * inv, hi_f(accO[o2]) * inv,
                                   hi_f(accB[o2]) * inv);
    }
}

typedef CUresult (*TmapEncodeFn)(
    CUtensorMap*, CUtensorMapDataType, cuuint32_t, void*,
    const cuuint64_t*, const cuuint64_t*, const cuuint32_t*, const cuuint32_t*,
    CUtensorMapInterleave, CUtensorMapSwizzle, CUtensorMapL2promotion,
    CUtensorMapFloatOOBfill);

extern "C" void kernel_launch(void* const* d_in, const int* in_sizes, int n_in,
                              void* d_out, int out_size) {
    (void)in_sizes; (void)n_in; (void)out_size;
    void* first_p  = d_in[0];
    void* second_p = d_in[1];
    float* out = (float*)d_out;

    // Fetch cuTensorMapEncodeTiled via cudart (no -lcuda link dependency)
    void* sym = nullptr;
    cudaDriverEntryPointQueryResult qr;
    cudaGetDriverEntryPointByVersion("cuTensorMapEncodeTiled", &sym, 12000,
                                     cudaEnableDefault, &qr);
    TmapEncodeFn enc = (TmapEncodeFn)sym;

    cuuint64_t dims[4]    = { WW, HH, CCT, BB };
    cuuint64_t strides[3] = { (cuuint64_t)WW * 4,
                              (cuuint64_t)HH * WW * 4,
                              (cuuint64_t)CCT * HH * WW * 4 };
    cuuint32_t es[4]   = { 1, 1, 1, 1 };
    cuuint32_t boxS[4] = { SSTR, SROWS, CCH, 1 };   // 40 x 12 x 8 x 1
    cuuint32_t boxF[4] = { TW, TH, CCH, 1 };        // 32 x 4 x 8 x 1

    CUtensorMap tmS, tmF;
    enc(&tmS, CU_TENSOR_MAP_DATA_TYPE_FLOAT32, 4, second_p,
        dims, strides, boxS, es,
        CU_TENSOR_MAP_INTERLEAVE_NONE, CU_TENSOR_MAP_SWIZZLE_NONE,
        CU_TENSOR_MAP_L2_PROMOTION_L2_256B, CU_TENSOR_MAP_FLOAT_OOB_FILL_NONE);
    enc(&tmF, CU_TENSOR_MAP_DATA_TYPE_FLOAT32, 4, first_p,
        dims, strides, boxF, es,
        CU_TENSOR_MAP_INTERLEAVE_NONE, CU_TENSOR_MAP_SWIZZLE_NONE,
        CU_TENSOR_MAP_L2_PROMOTION_L2_256B, CU_TENSOR_MAP_FLOAT_OOB_FILL_NONE);

    cudaFuncSetAttribute(costvol_kernel,
                         cudaFuncAttributeMaxDynamicSharedMemorySize, SMEM_BYTES);

    dim3 grid(WW / TW, HH / TH, BB);   // (4,32,8) = 1024 blocks
    costvol_kernel<<<grid, NT, SMEM_BYTES>>>(tmF, tmS, out);
}

// round 17
// speedup vs baseline: 1.5259x; 1.0985x over previous
#include <cuda_runtime.h>
#include <cuda.h>
#include <cstdint>
#include <cstddef>

// Problem constants
#define BB 8
#define CCT 128
#define HH 128
#define WW 128
#define RR 4
#define NOFF 81

// Tiling: 4x32 pixel tile, 4 px/thread, 32 threads per dy-group, 9 groups
// 288 threads/CTA, 3 CTAs per SM; scalar boundary FFMAs (zero ALU packs)
#define TH 4
#define TW 32
#define NGROUP 9
#define NT (NGROUP * 32)      // 288 threads, 9 warps
#define CCH 8                 // channels per chunk
#define NCHUNK (CCT / CCH)    // 16
#define NB 3                  // ring buffers; prefetch distance 2

// Shared layout (floats) — TMA box-dense strides
#define FSTR 32               // first row stride (= box width)
#define SSTR 40               // second row stride (= box width)
#define SROWS 12
#define F_CH (TH * FSTR)                  // 128
#define S_CH (SROWS * SSTR)               // 480
#define F_BUF (CCH * F_CH)                // 1024 fl = 4096 B
#define S_BUF (CCH * S_CH)                // 3840 fl = 15360 B
#define F_OFF 0
#define S_OFF (NB * F_BUF)                // 3072 fl
#define SMEM_FLOATS (S_OFF + NB * S_BUF)  // 14592 fl
#define SMEM_BYTES (SMEM_FLOATS * 4)      // 58368 B (x3 CTAs = 175KB/SM)
#define TX_BYTES ((F_BUF + S_BUF) * 4)    // 19456 B per chunk

typedef unsigned long long u64;

__device__ __forceinline__ u64 pk2(float lo, float hi) {
    u64 r;
    asm("mov.b64 %0, {%1, %2};" : "=l"(r) : "f"(lo), "f"(hi));
    return r;
}
__device__ __forceinline__ float lo_f(u64 v) { return __uint_as_float((unsigned)v); }
__device__ __forceinline__ float hi_f(u64 v) { return __uint_as_float((unsigned)(v >> 32)); }

__device__ __forceinline__ void fma2(u64& d, u64 a, u64 b) {
    asm("fma.rn.f32x2 %0, %1, %2, %0;" : "+l"(d) : "l"(a), "l"(b));
}
__device__ __forceinline__ void mbar_init(unsigned a, unsigned cnt) {
    asm volatile("mbarrier.init.shared.b64 [%0], %1;" :: "r"(a), "r"(cnt) : "memory");
}
__device__ __forceinline__ void mbar_arrive(unsigned a) {
    asm volatile("mbarrier.arrive.shared.b64 _, [%0];" :: "r"(a) : "memory");
}
__device__ __forceinline__ void mbar_arrive_tx(unsigned a, unsigned bytes) {
    asm volatile("mbarrier.arrive.expect_tx.shared.b64 _, [%0], %1;"
                 :: "r"(a), "r"(bytes) : "memory");
}
__device__ __forceinline__ void mbar_wait(unsigned a, unsigned ph) {
    asm volatile(
        "{\n\t.reg .pred p;\n"
        "W_%=:\n\t"
        "mbarrier.try_wait.parity.acquire.cta.shared::cta.b64 p, [%0], %1, 0x989680;\n\t"
        "@!p bra W_%=;\n\t}"
        :: "r"(a), "r"(ph) : "memory");
}
__device__ __forceinline__ void tma4d(unsigned dst, const CUtensorMap* tm,
                                      int x, int y, int z, int w, unsigned mbar) {
    asm volatile(
        "cp.async.bulk.tensor.4d.shared::cta.global.tile.mbarrier::complete_tx::bytes "
        "[%0], [%1, {%2, %3, %4, %5}], [%6];"
        :: "r"(dst), "l"(tm), "r"(x), "r"(y), "r"(z), "r"(w), "r"(mbar)
        : "memory");
}

__global__ void __launch_bounds__(NT, 3)
costvol_kernel(const __grid_constant__ CUtensorMap tmF,
               const __grid_constant__ CUtensorMap tmS,
               float* __restrict__ out) {
    extern __shared__ __align__(128) float smem[];
    __shared__ __align__(8) u64 mbar[2 * NB];   // [0..NB) full, [NB..2NB) empty

    const int tid = threadIdx.x;
    const int g   = tid >> 5;            // dy index 0..8
    const int lid = tid & 31;
    const int lh  = lid >> 3;            // local row 0..3
    const int lw  = (lid & 7) << 2;      // local col base {0,4,...,28}
    const int lane = tid & 31;

    const int w0 = blockIdx.x * TW;
    const int h0 = blockIdx.y * TH;
    const int bz = blockIdx.z;

    const unsigned smem_u = (unsigned)__cvta_generic_to_shared(smem);
    const unsigned mb0    = (unsigned)__cvta_generic_to_shared(mbar);

    // ---------- mbarrier init ----------
    if (tid == 0) {
#pragma unroll
        for (int b = 0; b < NB; b++) {
            mbar_init(mb0 + b * 8, 1);               // full[b]: producer arrive
            mbar_init(mb0 + (NB + b) * 8, NGROUP);   // empty[b]: 9 warp arrives
        }
    }
    __syncthreads();

    // ---------- producer: one TMA pair per chunk ----------
    auto issue = [&](int c, int b) {
        const unsigned fullb = mb0 + b * 8;
        mbar_arrive_tx(fullb, TX_BYTES);
        tma4d(smem_u + (S_OFF + b * S_BUF) * 4, &tmS,
              w0 - RR, h0 - RR, c * CCH, bz, fullb);
        tma4d(smem_u + (F_OFF + b * F_BUF) * 4, &tmF,
              w0, h0, c * CCH, bz, fullb);
    };

    if (tid == 0) { issue(0, 0); issue(1, 1); }

    // ---------- accumulators (4 px) ----------
    u64 accE[5][2];           // even dx = 2e; pixel pairs (0,1)(2,3)
    u64 accO[4];              // odd dx = 2o+1; pixel pair (1,2)
    float acc0[4], acc3[4];   // odd-dx boundary pixels 0 and 3 (scalar, zero packs)
#pragma unroll
    for (int e = 0; e < 5; e++) { accE[e][0] = 0ULL; accE[e][1] = 0ULL; }
#pragma unroll
    for (int o = 0; o < 4; o++) { accO[o] = 0ULL; acc0[o] = 0.f; acc3[o] = 0.f; }

    const float* Fbase = smem + F_OFF + lh * FSTR + lw;
    const float* Sbase = smem + S_OFF + (lh + g) * SSTR + lw;

    // pipeline cursors (stage, phase)
    int cstage = 0, cph = 0;          // consumer
    int pstage = 2, pph = 0;          // producer (chunks 0,1 already issued)

#pragma unroll 1
    for (int cc = 0; cc < NCHUNK; cc++) {
        // producer duty: prefetch chunk cc+2 into buffer pstage
        const int c = cc + 2;
        if (c < NCHUNK) {
            if (tid == 0) {
                if (c >= NB)
                    mbar_wait(mb0 + (NB + pstage) * 8, (unsigned)(pph ^ 1));
                issue(c, pstage);
            }
            if (++pstage == NB) { pstage = 0; pph ^= 1; }
        }

        // consume: wait until this chunk's TMA completed
        mbar_wait(mb0 + cstage * 8, (unsigned)cph);

        const float* Fp = Fbase + cstage * F_BUF;
        const float* Sp = Sbase + cstage * S_BUF;

#pragma unroll
        for (int ch = 0; ch < CCH; ch++) {
            const float* fptr = Fp + ch * F_CH;
            const float* sptr = Sp + ch * S_CH;

            // first: 2 aligned pairs + scalar views; 1 odd-pack only
            ulonglong2 fA = *(const ulonglong2*)fptr;
            u64 fp0 = fA.x, fp1 = fA.y;
            float f0 = lo_f(fp0), f1 = hi_f(fp0);
            float f2 = lo_f(fp1), f3 = hi_f(fp1);
            u64 op0 = pk2(f1, f2);

            // second window: 12 floats = 6 aligned pairs
            ulonglong2 wA = *(const ulonglong2*)sptr;
            ulonglong2 wB = *(const ulonglong2*)(sptr + 4);
            ulonglong2 wC = *(const ulonglong2*)(sptr + 8);
            u64 wp[6] = { wA.x, wA.y, wB.x, wB.y, wC.x, wC.y };

            // even dx = 2e: aligned, zero packs
#pragma unroll
            for (int e = 0; e < 5; e++) {
                fma2(accE[e][0], fp0, wp[e]);
                fma2(accE[e][1], fp1, wp[e + 1]);
            }
            // odd dx = 2o+1: middle pair aligned; boundaries scalar on fma pipe
#pragma unroll
            for (int o = 0; o < 4; o++) {
                fma2(accO[o], op0, wp[o + 1]);
                acc0[o] = fmaf(f0, hi_f(wp[o]),     acc0[o]);   // w[2o+1]
                acc3[o] = fmaf(f3, lo_f(wp[o + 2]), acc3[o]);   // w[2o+4]
            }
        }

        // release buffer (warp-granular)
        __syncwarp();
        if (lane == 0) mbar_arrive(mb0 + (NB + cstage) * 8);
        if (++cstage == NB) { cstage = 0; cph ^= 1; }
    }

    // ---------- store: mean over C ----------
    const float inv = 1.0f / (float)CCT;
    const size_t row_base = ((size_t)bz * NOFF) * HH * WW
                          + (size_t)(h0 + lh) * WW + (w0 + lw);
#pragma unroll
    for (int e = 0; e < 5; e++) {
        int o = g * 9 + 2 * e;
        float* op = out + row_base + (size_t)o * HH * WW;
        *(float4*)op = make_float4(lo_f(accE[e][0]) * inv, hi_f(accE[e][0]) * inv,
                                   lo_f(accE[e][1]) * inv, hi_f(accE[e][1]) * inv);
    }
#pragma unroll
    for (int o2 = 0; o2 < 4; o2++) {
        int o = g * 9 + 2 * o2 + 1;
        float* op = out + row_base + (size_t)o * HH * WW;
        *(float4*)op = make_float4(acc0[o2] * inv,
                                   lo_f(accO[o2]) * inv, hi_f(accO[o2]) * inv,
                                   acc3[o2] * inv);
    }
}

typedef CUresult (*TmapEncodeFn)(
    CUtensorMap*, CUtensorMapDataType, cuuint32_t, void*,
    const cuuint64_t*, const cuuint64_t*, const cuuint32_t*, const cuuint32_t*,
    CUtensorMapInterleave, CUtensorMapSwizzle, CUtensorMapL2promotion,
    CUtensorMapFloatOOBfill);

extern "C" void kernel_launch(void* const* d_in, const int* in_sizes, int n_in,
                              void* d_out, int out_size) {
    (void)in_sizes; (void)n_in; (void)out_size;
    void* first_p  = d_in[0];
    void* second_p = d_in[1];
    float* out = (float*)d_out;

    // Fetch cuTensorMapEncodeTiled via cudart (no -lcuda link dependency)
    void* sym = nullptr;
    cudaDriverEntryPointQueryResult qr;
    cudaGetDriverEntryPointByVersion("cuTensorMapEncodeTiled", &sym, 12000,
                                     cudaEnableDefault, &qr);
    TmapEncodeFn enc = (TmapEncodeFn)sym;

    cuuint64_t dims[4]    = { WW, HH, CCT, BB };
    cuuint64_t strides[3] = { (cuuint64_t)WW * 4,
                              (cuuint64_t)HH * WW * 4,
                              (cuuint64_t)CCT * HH * WW * 4 };
    cuuint32_t es[4]   = { 1, 1, 1, 1 };
    cuuint32_t boxS[4] = { SSTR, SROWS, CCH, 1 };   // 40 x 12 x 8 x 1
    cuuint32_t boxF[4] = { TW, TH, CCH, 1 };        // 32 x 4 x 8 x 1

    CUtensorMap tmS, tmF;
    enc(&tmS, CU_TENSOR_MAP_DATA_TYPE_FLOAT32, 4, second_p,
        dims, strides, boxS, es,
        CU_TENSOR_MAP_INTERLEAVE_NONE, CU_TENSOR_MAP_SWIZZLE_NONE,
        CU_TENSOR_MAP_L2_PROMOTION_L2_256B, CU_TENSOR_MAP_FLOAT_OOB_FILL_NONE);
    enc(&tmF, CU_TENSOR_MAP_DATA_TYPE_FLOAT32, 4, first_p,
        dims, strides, boxF, es,
        CU_TENSOR_MAP_INTERLEAVE_NONE, CU_TENSOR_MAP_SWIZZLE_NONE,
        CU_TENSOR_MAP_L2_PROMOTION_L2_256B, CU_TENSOR_MAP_FLOAT_OOB_FILL_NONE);

    cudaFuncSetAttribute(costvol_kernel,
                         cudaFuncAttributeMaxDynamicSharedMemorySize, SMEM_BYTES);

    dim3 grid(WW / TW, HH / TH, BB);   // (4,32,8) = 1024 blocks
    costvol_kernel<<<grid, NT, SMEM_BYTES>>>(tmF, tmS, out);
}